// round 8
// baseline (speedup 1.0000x reference)
#include <cuda_runtime.h>
#include <cuda_bf16.h>

#define BB 2048
#define TT 128
#define DD 512
#define CHK 32                    // timesteps per scan chunk
#define NCHK (TT / CHK)           // 4 chunks

// Scratch: gi transposed as [(t*3+g)*B + b]  -> coalesced reads in the scan.
__device__ float g_giT[3 * TT * BB];

__device__ __forceinline__ float tanh_fast(float x) {
    float y;
    asm("tanh.approx.f32 %0, %1;" : "=f"(y) : "f"(x));
    return y;
}

// ---------------------------------------------------------------------------
// Kernel A: gi[b,t,g] = sum_d x[b,t,d] * w_ih[g,d]
// One warp per 2 rows (8 outstanding LDG.128), weights in regs, streaming
// (.cs) loads for x: 512 MB read once, don't thrash L2.
// ---------------------------------------------------------------------------
__global__ void __launch_bounds__(256) gi_kernel(const float* __restrict__ x,
                                                 const float* __restrict__ w_ih) {
    const int lane   = threadIdx.x & 31;
    const int warp   = (blockIdx.x * blockDim.x + threadIdx.x) >> 5;
    const int nwarps = (gridDim.x * blockDim.x) >> 5;

    float4 wr[4], wz[4], wn[4];
    const float4* w4 = (const float4*)w_ih;
#pragma unroll
    for (int i = 0; i < 4; i++) {
        int j = lane + 32 * i;
        wr[i] = w4[0 * (DD / 4) + j];
        wz[i] = w4[1 * (DD / 4) + j];
        wn[i] = w4[2 * (DD / 4) + j];
    }

    const int total = BB * TT;
    for (int row = warp * 2; row < total; row += nwarps * 2) {
        const int r0 = row, r1 = row + 1;
        const int t0 = r0 >> 11, b0 = r0 & (BB - 1);
        const int t1 = r1 >> 11, b1 = r1 & (BB - 1);
        const float4* xr0 = (const float4*)(x + ((size_t)b0 * TT + t0) * DD);
        const float4* xr1 = (const float4*)(x + ((size_t)b1 * TT + t1) * DD);

        // Front-batch all 8 streaming loads (MLP=8 per lane).
        float4 v0[4], v1[4];
#pragma unroll
        for (int i = 0; i < 4; i++) v0[i] = __ldcs(&xr0[lane + 32 * i]);
#pragma unroll
        for (int i = 0; i < 4; i++) v1[i] = __ldcs(&xr1[lane + 32 * i]);

        float sr0 = 0.f, sz0 = 0.f, sn0 = 0.f;
        float sr1 = 0.f, sz1 = 0.f, sn1 = 0.f;
#pragma unroll
        for (int i = 0; i < 4; i++) {
            sr0 += v0[i].x * wr[i].x + v0[i].y * wr[i].y + v0[i].z * wr[i].z + v0[i].w * wr[i].w;
            sz0 += v0[i].x * wz[i].x + v0[i].y * wz[i].y + v0[i].z * wz[i].z + v0[i].w * wz[i].w;
            sn0 += v0[i].x * wn[i].x + v0[i].y * wn[i].y + v0[i].z * wn[i].z + v0[i].w * wn[i].w;
            sr1 += v1[i].x * wr[i].x + v1[i].y * wr[i].y + v1[i].z * wr[i].z + v1[i].w * wr[i].w;
            sz1 += v1[i].x * wz[i].x + v1[i].y * wz[i].y + v1[i].z * wz[i].z + v1[i].w * wz[i].w;
            sn1 += v1[i].x * wn[i].x + v1[i].y * wn[i].y + v1[i].z * wn[i].z + v1[i].w * wn[i].w;
        }
#pragma unroll
        for (int off = 16; off; off >>= 1) {
            sr0 += __shfl_down_sync(0xffffffffu, sr0, off);
            sz0 += __shfl_down_sync(0xffffffffu, sz0, off);
            sn0 += __shfl_down_sync(0xffffffffu, sn0, off);
            sr1 += __shfl_down_sync(0xffffffffu, sr1, off);
            sz1 += __shfl_down_sync(0xffffffffu, sz1, off);
            sn1 += __shfl_down_sync(0xffffffffu, sn1, off);
        }
        if (lane == 0) {
            g_giT[(t0 * 3 + 0) * BB + b0] = sr0;
            g_giT[(t0 * 3 + 1) * BB + b0] = sz0;
            g_giT[(t0 * 3 + 2) * BB + b0] = sn0;
            g_giT[(t1 * 3 + 0) * BB + b1] = sr1;
            g_giT[(t1 * 3 + 1) * BB + b1] = sz1;
            g_giT[(t1 * 3 + 2) * BB + b1] = sn1;
        }
    }
}

// ---------------------------------------------------------------------------
// Kernel B: GRU scan. Block = 256 threads, handles 32 batch rows.
// Pipelined: warps 1-7 stage chunk c+1 into smem WHILE warp 0 scans chunk c.
// Chain per step ~44 cy: h' = fma(omz, n, z*h), omz/zh computed parallel to
// the n-tanh. Reduction over b after the loop, 16 t's per warp.
// ---------------------------------------------------------------------------
__global__ void __launch_bounds__(256) scan_kernel(const float* __restrict__ h0,
                                                   const float* __restrict__ w_hh,
                                                   const float* __restrict__ b_ih,
                                                   const float* __restrict__ b_hh,
                                                   float* __restrict__ out) {
    __shared__ float sg[TT * 3 * 32];               // 48 KB: [(t*3+g)*32 + lane]
    const int tid  = threadIdx.x;
    const int lane = tid & 31;
    const int wid  = tid >> 5;
    const int b0   = blockIdx.x * 32;

    // Stage chunk 0 (rows 0..95): all 8 warps, 12 rows each.
#pragma unroll
    for (int r = wid; r < CHK * 3; r += 8)
        sg[r * 32 + lane] = g_giT[(size_t)r * BB + b0 + lane];
    __syncthreads();

    const float whh0h = 0.5f * w_hh[0];
    const float whh1h = 0.5f * w_hh[1];
    const float whh2  = w_hh[2];
    const float c0h   = 0.5f * (b_ih[0] + b_hh[0]);
    const float c1h   = 0.5f * (b_ih[1] + b_hh[1]);
    const float cn    = b_ih[2];
    const float ch2   = b_hh[2];

    float h = h0[b0 + lane];

    for (int c = 0; c < NCHK; c++) {
        if (wid > 0) {
            // Warps 1-7: stage chunk c+1 (96 rows) while warp 0 scans chunk c.
            if (c + 1 < NCHK) {
                const int rbase = (c + 1) * CHK * 3;
                for (int r = wid - 1; r < CHK * 3; r += 7)
                    sg[(rbase + r) * 32 + lane] =
                        g_giT[(size_t)(rbase + r) * BB + b0 + lane];
            }
        } else {
            // Warp 0: scan 32 steps of chunk c.
            const int t0 = c * CHK;
            float gr = sg[(t0 * 3 + 0) * 32 + lane];
            float gz = sg[(t0 * 3 + 1) * 32 + lane];
            float gn = sg[(t0 * 3 + 2) * 32 + lane];
#pragma unroll
            for (int k = 0; k < CHK; k++) {
                const int t = t0 + k;
                // Prefetch next step within the chunk (off-chain LDS).
                float ngr = 0.f, ngz = 0.f, ngn = 0.f;
                if (k + 1 < CHK) {
                    ngr = sg[((t + 1) * 3 + 0) * 32 + lane];
                    ngz = sg[((t + 1) * 3 + 1) * 32 + lane];
                    ngn = sg[((t + 1) * 3 + 2) * 32 + lane];
                }

                // Off-chain folds.
                const float grh = fmaf(gr, 0.5f, c0h);
                const float gzh = fmaf(gz, 0.5f, c1h);
                const float gnc = gn + cn;

                // Chain (~44 cy): FFMA->MUFU(r) -> FFMA -> MUFU(n) -> FFMA.
                const float th_r = tanh_fast(fmaf(h, whh0h, grh));
                const float th_z = tanh_fast(fmaf(h, whh1h, gzh)); // parallel
                const float ghnh = 0.5f * fmaf(h, whh2, ch2);      // parallel
                const float n    = tanh_fast(fmaf(th_r, ghnh, gnc + ghnh));
                const float z    = fmaf(th_z, 0.5f, 0.5f);         // ready early
                const float zh   = z * h;                          // parallel to n
                const float omz  = fmaf(th_z, -0.5f, 0.5f);        // 1 - z
                h = fmaf(omz, n, zh);

                sg[(t * 3 + 2) * 32 + lane] = h;    // reuse consumed slot
                gr = ngr; gz = ngz; gn = ngn;
            }
        }
        __syncthreads();
    }

    // Reduction over lanes, 16 t's per warp, all warps.
    const float inv = 1.0f / (float)BB;
#pragma unroll
    for (int j = 0; j < 16; j++) {
        const int t = wid * 16 + j;
        float s = sg[(t * 3 + 2) * 32 + lane];
#pragma unroll
        for (int off = 16; off; off >>= 1)
            s += __shfl_down_sync(0xffffffffu, s, off);
        if (lane == 0)
            atomicAdd(out + t, s * inv);
    }
}

// ---------------------------------------------------------------------------
// Launch: inputs per metadata order: x, h0, w_ih, w_hh, b_ih, b_hh
// ---------------------------------------------------------------------------
extern "C" void kernel_launch(void* const* d_in, const int* in_sizes, int n_in,
                              void* d_out, int out_size) {
    const float* x    = (const float*)d_in[0];
    const float* h0   = (const float*)d_in[1];
    const float* w_ih = (const float*)d_in[2];
    const float* w_hh = (const float*)d_in[3];
    const float* b_ih = (const float*)d_in[4];
    const float* b_hh = (const float*)d_in[5];
    float* out = (float*)d_out;

    cudaMemsetAsync(out, 0, (size_t)out_size * sizeof(float));

    gi_kernel<<<4096, 256>>>(x, w_ih);
    scan_kernel<<<BB / 32, 256>>>(h0, w_hh, b_ih, b_hh, out);
}